// round 5
// baseline (speedup 1.0000x reference)
#include <cuda_runtime.h>

// LearnableConvCensus: depthwise 3x3 conv (multiplier 8) -> sigmoid -> mean over 8.
// B=4, C=64, H=W=256, pad=1.
//
// sigmoid(z) = 0.5 + 0.5*tanh(z/2); fold 0.5*temperature[c] into pre-scaled
// weights/bias. out = 0.5 + (sum_m tanh_m) / 16.
//
// R5: per-multiplier-pair phase loop (36 FFMA2 then 8 tanh per phase) gives
// fine-grained FMA/MUFU overlap without a 64-reg acc double buffer; regs cut
// to fit 6 CTAs/SM (24 warps) — dead issue cycles were the R4 limiter.

#define B_ 4
#define C_ 64
#define H_ 256
#define W_ 256
#define R_ 16                 // output rows per block
#define NROWS (R_ + 2)        // tile rows incl. halo
#define SROW 264              // smem row stride in floats

typedef unsigned long long ull;

__device__ __forceinline__ ull pack2(float lo, float hi) {
    ull r;
    asm("mov.b64 %0, {%1, %2};" : "=l"(r) : "f"(lo), "f"(hi));
    return r;
}
__device__ __forceinline__ ull dup2(float v) {
    ull r;
    asm("mov.b64 %0, {%1, %1};" : "=l"(r) : "f"(v));
    return r;
}
__device__ __forceinline__ void unpack2(ull v, float& lo, float& hi) {
    asm("mov.b64 {%0, %1}, %2;" : "=f"(lo), "=f"(hi) : "l"(v));
}
__device__ __forceinline__ void fma2(ull& acc, ull a, ull b) {
    asm("fma.rn.f32x2 %0, %1, %2, %0;" : "+l"(acc) : "l"(a), "l"(b));
}
__device__ __forceinline__ float tanh_fast(float x) {
    float y;
    asm("tanh.approx.f32 %0, %1;" : "=f"(y) : "f"(x));
    return y;
}

__global__ __launch_bounds__(128, 6)
void census_kernel(const float* __restrict__ x, const float* __restrict__ w,
                   const float* __restrict__ bias, const float* __restrict__ temp,
                   float* __restrict__ out) {
    __shared__ float smem[NROWS * SROW];
    __shared__ ull   wsm[4][10];    // [pair p][tap k], pre-scaled pairs; [9] pad
    __shared__ ull   bsm[4];        // bias pairs

    const int bid   = blockIdx.x;
    const int strip = bid & 15;         // H_/R_ = 16 strips
    const int c     = (bid >> 4) & 63;
    const int b     = bid >> 10;
    const int h0    = strip * R_;
    const int tid   = threadIdx.x;

    const float* xp = x + ((size_t)(b * C_ + c) * H_) * W_;

    // ---- weight prep: w layout HWIO flattened w[(kh*3+kw)*512 + c*8 + m]
    if (tid < 40) {
        const float sc = 0.5f * __ldg(&temp[c]);
        if (tid < 36) {
            const int k = tid % 9, p = tid / 9;
            const float w0 = __ldg(&w[k * 512 + (c << 3) + 2 * p])     * sc;
            const float w1 = __ldg(&w[k * 512 + (c << 3) + 2 * p + 1]) * sc;
            wsm[p][k] = pack2(w0, w1);
        } else {
            const int p = tid - 36;
            const float b0 = __ldg(&bias[(c << 3) + 2 * p])     * sc;
            const float b1 = __ldg(&bias[(c << 3) + 2 * p + 1]) * sc;
            bsm[p] = pack2(b0, b1);
        }
    }

    // ---- tile load: smem[r][4 + wcol] = x[h0 + r - 1][wcol]; cols 3 & 260 are
    // the zero conv padding (tiles span the full width). 18*64 float4 / 128 thr.
    #pragma unroll
    for (int i = tid; i < NROWS * 64; i += 128) {
        const int r  = i >> 6;
        const int c4 = (i & 63) << 2;
        const int gh = h0 + r - 1;
        float4 v = make_float4(0.f, 0.f, 0.f, 0.f);
        if (gh >= 0 && gh < H_) v = *(const float4*)(xp + gh * W_ + c4);
        *(float4*)&smem[r * SROW + 4 + c4] = v;
    }
    if (tid < NROWS) {
        smem[tid * SROW + 3]   = 0.f;
        smem[tid * SROW + 260] = 0.f;
    }
    __syncthreads();

    const ull bp0 = bsm[0], bp1 = bsm[1], bp2 = bsm[2], bp3 = bsm[3];

    const int tx = tid & 63;   // 64 threads across width, 4 cols each
    const int ty = tid >> 6;   // 2 row-groups
    float* outp = out + (((size_t)(b * C_ + c) * H_) + h0) * W_ + (tx << 2);

    #pragma unroll 1
    for (int r = ty; r < R_; r += 2) {
        // ---- window: d[kh][i] = dup(x[r+kh-1][4tx-1+i]), i=0..5
        ull d[3][6];
        #pragma unroll
        for (int kh = 0; kh < 3; kh++) {
            const float* rowp = &smem[(r + kh) * SROW + (tx << 2)];
            const float  wm1 = rowp[3];
            const float4 f4  = *(const float4*)(rowp + 4);
            const float  wp4 = rowp[8];
            d[kh][0] = dup2(wm1);
            d[kh][1] = dup2(f4.x);
            d[kh][2] = dup2(f4.y);
            d[kh][3] = dup2(f4.z);
            d[kh][4] = dup2(f4.w);
            d[kh][5] = dup2(wp4);
        }

        float s0 = 0.f, s1 = 0.f, s2 = 0.f, s3 = 0.f;

        // ---- phase loop over multiplier pairs: 36 FFMA2 then 8 tanh each.
        #pragma unroll
        for (int p = 0; p < 4; p++) {
            const ulonglong2 wA = *(const ulonglong2*)&wsm[p][0];  // taps 0,1
            const ulonglong2 wB = *(const ulonglong2*)&wsm[p][2];  // taps 2,3
            const ulonglong2 wC = *(const ulonglong2*)&wsm[p][4];  // taps 4,5
            const ulonglong2 wD = *(const ulonglong2*)&wsm[p][6];  // taps 6,7
            const ull        w8 = wsm[p][8];
            const ull wt[9] = {wA.x, wA.y, wB.x, wB.y, wC.x, wC.y, wD.x, wD.y, w8};

            const ull bp = (p == 0) ? bp0 : (p == 1) ? bp1 : (p == 2) ? bp2 : bp3;
            ull a0 = bp, a1 = bp, a2 = bp, a3 = bp;

            #pragma unroll
            for (int kh = 0; kh < 3; kh++) {
                #pragma unroll
                for (int kw = 0; kw < 3; kw++) {
                    const ull wk = wt[kh * 3 + kw];
                    fma2(a0, d[kh][kw + 0], wk);
                    fma2(a1, d[kh][kw + 1], wk);
                    fma2(a2, d[kh][kw + 2], wk);
                    fma2(a3, d[kh][kw + 3], wk);
                }
            }

            float v0, v1;
            unpack2(a0, v0, v1); s0 += tanh_fast(v0) + tanh_fast(v1);
            unpack2(a1, v0, v1); s1 += tanh_fast(v0) + tanh_fast(v1);
            unpack2(a2, v0, v1); s2 += tanh_fast(v0) + tanh_fast(v1);
            unpack2(a3, v0, v1); s3 += tanh_fast(v0) + tanh_fast(v1);
        }

        float4 o;
        o.x = fmaf(s0, 0.0625f, 0.5f);
        o.y = fmaf(s1, 0.0625f, 0.5f);
        o.z = fmaf(s2, 0.0625f, 0.5f);
        o.w = fmaf(s3, 0.0625f, 0.5f);
        *(float4*)(outp + r * W_) = o;
    }
}

extern "C" void kernel_launch(void* const* d_in, const int* in_sizes, int n_in,
                              void* d_out, int out_size) {
    const float* x    = (const float*)d_in[0];
    const float* w    = (const float*)d_in[1];
    const float* bias = (const float*)d_in[2];
    const float* temp = (const float*)d_in[3];
    float* out = (float*)d_out;

    const int grid = B_ * C_ * (H_ / R_);   // 4*64*16 = 4096 blocks
    census_kernel<<<grid, 128>>>(x, w, bias, temp, out);
}